// round 10
// baseline (speedup 1.0000x reference)
#include <cuda_runtime.h>
#include <cuda_fp16.h>
#include <cstdint>
#include <cstddef>

#define C_DIM 512
#define NSP   4096
#define BATCH 2
#define NGROUPS 32
#define GCH 16

#define MT 256
#define NT 128
#define NTH 512
#define KC 64                          // halves per chunk
#define KPADW 36                       // words per row (32 data + 4 pad)
#define AW (MT * KPADW)                // 9216 words
#define BW (NT * KPADW)                // 4608 words
#define STW (AW + BW)                  // words per stage
#define NSTAGE 3
#define SMEM_DYN (NSTAGE * STW * 4)    // 165888 B

#define BO  ((size_t)C_DIM * NSP)
#define SO  ((size_t)NSP * NSP)
#define WO  ((size_t)C_DIM * C_DIM)

// ---------------- scratch ----------------
__device__ __half g_hnT[(size_t)BATCH * NSP * C_DIM];   // [b][token][cin]
__device__ __half g_q  [(size_t)BATCH * NSP * C_DIM];
__device__ __half g_k  [(size_t)BATCH * NSP * C_DIM];
__device__ __half g_v  [(size_t)BATCH * C_DIM * NSP];   // [b][cout][token]
__device__ __half g_ao [(size_t)BATCH * NSP * C_DIM];
__device__ __half g_at [(size_t)BATCH * NSP * NSP];     // exp(scores), unnormalized
__device__ float  g_rsum[BATCH * NSP];
__device__ float  g_part[BATCH * NGROUPS * 2];          // GN partial s, s2
__device__ __half g_wh [4 * C_DIM * C_DIM];
__device__ float  g_bqkv[3 * C_DIM];
__device__ float  g_mean[BATCH * NGROUPS];
__device__ float  g_inv [BATCH * NGROUPS];

__device__ __forceinline__ void cp16(uint32_t smem_dst, const void* gsrc) {
    asm volatile("cp.async.cg.shared.global [%0], [%1], 16;" :: "r"(smem_dst), "l"(gsrc));
}
#define CP_COMMIT() asm volatile("cp.async.commit_group;" ::: "memory")
#define CP_WAIT2()  asm volatile("cp.async.wait_group 2;" ::: "memory")

__device__ __forceinline__ void mma_f16(float* d, const uint32_t* a, const uint32_t* b) {
    asm volatile(
        "mma.sync.aligned.m16n8k16.row.col.f32.f16.f16.f32 "
        "{%0,%1,%2,%3}, {%4,%5,%6,%7}, {%8,%9}, {%0,%1,%2,%3};"
        : "+f"(d[0]), "+f"(d[1]), "+f"(d[2]), "+f"(d[3])
        : "r"(a[0]), "r"(a[1]), "r"(a[2]), "r"(a[3]), "r"(b[0]), "r"(b[1]));
}
__device__ __forceinline__ void ldsm_x4(uint32_t& r0, uint32_t& r1, uint32_t& r2,
                                        uint32_t& r3, uint32_t addr) {
    asm volatile("ldmatrix.sync.aligned.m8n8.x4.shared.b16 {%0,%1,%2,%3}, [%4];"
                 : "=r"(r0), "=r"(r1), "=r"(r2), "=r"(r3) : "r"(addr));
}

// ---------------- fp16 GEMM: 256x128 tile, 512 threads, cp.async 3-stage ----------------
// D[m,n] = alpha * sum_k A[m,k]*B[n,k]
// mode 0: at half [m][4096] = exp(D); atomicAdd row sums
// mode 1: C0 half [m][512] = D / rsum[m]
// mode 2: fused QKV: n<512 -> q; n<1024 -> k; else v trans [c][4096]
// mode 3: C0 float [n][4096] trans + bias[n] + resid
__global__ void __launch_bounds__(NTH, 1)
hgemm(const __half* __restrict__ A, size_t aBat, int lda,
      const __half* __restrict__ B, size_t bBat, int ldb,
      int K, float alpha, const float* __restrict__ bias,
      void* C0, void* C1, void* C2,
      const float* __restrict__ resid, float* __restrict__ rsum, int mode) {
    extern __shared__ uint32_t sm[];

    const int tid  = threadIdx.x;
    const int wid  = tid >> 5, lane = tid & 31;
    const int wm   = wid & 3;           // 0..3: 64-row strip
    const int wn   = wid >> 2;          // 0..3: 32-col strip
    const int g    = lane >> 2;
    const int t    = lane & 3;

    const int m0 = blockIdx.y * MT, n0 = blockIdx.x * NT;
    const int z  = blockIdx.z;
    A += z * aBat + (size_t)m0 * lda;
    B += z * bBat + (size_t)n0 * ldb;

    const int row  = tid >> 3;          // 0..63
    const int colw = (tid & 7) << 2;
    const int colh = (tid & 7) << 3;

    uint32_t smbase;
    asm("{ .reg .u64 t; cvta.to.shared.u64 t, %1; cvt.u32.u64 %0, t; }"
        : "=r"(smbase) : "l"((void*)sm));

    const uint32_t aoff = (((uint32_t)(wm * 64 + (lane & 15)) * KPADW) + ((lane >> 4) << 2)) * 4;
    const uint32_t boff = (((uint32_t)(wn * 32 + (lane & 7) + ((lane >> 4) << 3)) * KPADW)
                           + (((lane >> 3) & 1) << 2)) * 4;

    const int nch = K / KC;
    float acc[4][4][4] = {};

    #define ISSUE(cidx)  do {                                                       \
        const int _b  = (cidx) % NSTAGE;                                            \
        const int _kc = (cidx) * KC;                                                \
        uint32_t _sa = smbase + ((_b * STW) + row * KPADW + colw) * 4;              \
        uint32_t _sb = smbase + ((_b * STW) + AW + row * KPADW + colw) * 4;         \
        _Pragma("unroll")                                                           \
        for (int _i = 0; _i < 4; _i++)                                              \
            cp16(_sa + _i * 64 * KPADW * 4,                                         \
                 A + (size_t)(row + _i * 64) * lda + _kc + colh);                   \
        _Pragma("unroll")                                                           \
        for (int _i = 0; _i < 2; _i++)                                              \
            cp16(_sb + _i * 64 * KPADW * 4,                                         \
                 B + (size_t)(row + _i * 64) * ldb + _kc + colh);                   \
    } while (0)

    ISSUE(0); CP_COMMIT();
    ISSUE(1); CP_COMMIT();

    for (int c = 0; c < nch; c++) {
        if (c + 2 < nch) { ISSUE(c + 2); }
        CP_COMMIT();
        CP_WAIT2();
        __syncthreads();

        const uint32_t sA = smbase + (c % NSTAGE) * STW * 4;
        const uint32_t sB = sA + AW * 4;
        #pragma unroll
        for (int ks = 0; ks < 4; ks++) {
            uint32_t af[4][4], bf[4][2];
            #pragma unroll
            for (int mi = 0; mi < 4; mi++)
                ldsm_x4(af[mi][0], af[mi][1], af[mi][2], af[mi][3],
                        sA + aoff + mi * (16 * KPADW * 4) + ks * 32);
            #pragma unroll
            for (int nj = 0; nj < 2; nj++)
                ldsm_x4(bf[2 * nj][0], bf[2 * nj][1], bf[2 * nj + 1][0], bf[2 * nj + 1][1],
                        sB + boff + nj * (16 * KPADW * 4) + ks * 32);
            #pragma unroll
            for (int mi = 0; mi < 4; mi++)
                #pragma unroll
                for (int ni = 0; ni < 4; ni++)
                    mma_f16(acc[mi][ni], af[mi], bf[ni]);
        }
        __syncthreads();
    }
    #undef ISSUE

    // -------- epilogue --------
    #pragma unroll
    for (int mi = 0; mi < 4; mi++) {
        int m = m0 + wm * 64 + mi * 16 + g;
        float rs0 = 0.f, rs1 = 0.f;
        float ri0 = 1.f, ri1 = 1.f;
        if (mode == 1) {
            ri0 = __frcp_rn(rsum[z * NSP + m]);
            ri1 = __frcp_rn(rsum[z * NSP + m + 8]);
        }
        #pragma unroll
        for (int ni = 0; ni < 4; ni++) {
            const float* d = acc[mi][ni];
            int n = n0 + wn * 32 + ni * 8 + t * 2;
            float b0 = bias ? bias[n]     : 0.f;
            float b1 = bias ? bias[n + 1] : 0.f;
            float v0 = d[0] * alpha + b0;
            float v1 = d[1] * alpha + b1;
            float v2 = d[2] * alpha + b0;
            float v3 = d[3] * alpha + b1;
            if (mode == 0) {
                v0 = __expf(v0); v1 = __expf(v1);
                v2 = __expf(v2); v3 = __expf(v3);
                rs0 += v0 + v1; rs1 += v2 + v3;
                __half* o = (__half*)C0 + z * SO;
                *(__half2*)(o + (size_t)m * NSP + n)       = __floats2half2_rn(v0, v1);
                *(__half2*)(o + (size_t)(m + 8) * NSP + n) = __floats2half2_rn(v2, v3);
            } else if (mode == 1) {
                __half* o = (__half*)C0 + z * BO;
                *(__half2*)(o + (size_t)m * C_DIM + n)       = __floats2half2_rn(v0 * ri0, v1 * ri0);
                *(__half2*)(o + (size_t)(m + 8) * C_DIM + n) = __floats2half2_rn(v2 * ri1, v3 * ri1);
            } else if (mode == 2) {
                if (n < 1024) {
                    __half* o = (__half*)((n < 512) ? C0 : C1) + z * BO;
                    int nn = n & 511;
                    *(__half2*)(o + (size_t)m * C_DIM + nn)       = __floats2half2_rn(v0, v1);
                    *(__half2*)(o + (size_t)(m + 8) * C_DIM + nn) = __floats2half2_rn(v2, v3);
                } else {
                    __half* o = (__half*)C2 + z * BO;
                    int nn = n - 1024;
                    o[(size_t)nn * NSP + m]           = __float2half_rn(v0);
                    o[(size_t)(nn + 1) * NSP + m]     = __float2half_rn(v1);
                    o[(size_t)nn * NSP + m + 8]       = __float2half_rn(v2);
                    o[(size_t)(nn + 1) * NSP + m + 8] = __float2half_rn(v3);
                }
            } else {
                float* o = (float*)C0 + z * BO;
                const float* r = resid + z * BO;
                size_t o0 = (size_t)n * NSP + m;
                size_t o1 = (size_t)(n + 1) * NSP + m;
                o[o0]     = v0 + r[o0];
                o[o1]     = v1 + r[o1];
                o[o0 + 8] = v2 + r[o0 + 8];
                o[o1 + 8] = v3 + r[o1 + 8];
            }
        }
        if (mode == 0) {
            rs0 += __shfl_xor_sync(0xffffffffu, rs0, 1);
            rs0 += __shfl_xor_sync(0xffffffffu, rs0, 2);
            rs1 += __shfl_xor_sync(0xffffffffu, rs1, 1);
            rs1 += __shfl_xor_sync(0xffffffffu, rs1, 2);
            if (t == 0) {
                atomicAdd(&rsum[z * NSP + m], rs0);
                atomicAdd(&rsum[z * NSP + m + 8], rs1);
            }
        }
    }
}

// ---------------- zero rsum + GN partials ----------------
__global__ void __launch_bounds__(1024)
zero_scratch(float* __restrict__ rsum, float* __restrict__ part) {
    int i = blockIdx.x * 1024 + threadIdx.x;
    if (i < BATCH * NSP) rsum[i] = 0.f;
    if (i < BATCH * NGROUPS * 2) part[i] = 0.f;
}

// ---------------- block reduction ----------------
__device__ __forceinline__ float block_sum(float v) {
    __shared__ float smr[32];
    int w = threadIdx.x >> 5, l = threadIdx.x & 31;
    #pragma unroll
    for (int o = 16; o; o >>= 1) v += __shfl_xor_sync(0xffffffffu, v, o);
    __syncthreads();
    if (l == 0) smr[w] = v;
    __syncthreads();
    if (w == 0) {
        v = (l < (int)(blockDim.x >> 5)) ? smr[l] : 0.f;
        #pragma unroll
        for (int o = 16; o; o >>= 1) v += __shfl_xor_sync(0xffffffffu, v, o);
        if (l == 0) smr[0] = v;
    }
    __syncthreads();
    return smr[0];
}

// ---------------- GN partial stats: 512 blocks (8 slices per group) ----------------
__global__ void __launch_bounds__(256)
gn_part(const float* __restrict__ x, float* __restrict__ part) {
    const int grp = blockIdx.x >> 3;           // 0..63 (b*32+g)
    const int sl  = blockIdx.x & 7;
    const size_t base = (size_t)grp * GCH * NSP + (size_t)sl * (GCH * NSP / 8);
    const float4* xp = (const float4*)(x + base);
    const int NV = GCH * NSP / 8 / 4;          // 2048 float4
    float s = 0.f, s2 = 0.f;
    for (int i = threadIdx.x; i < NV; i += 256) {
        float4 v = xp[i];
        s  += v.x + v.y + v.z + v.w;
        s2 += v.x*v.x + v.y*v.y + v.z*v.z + v.w*v.w;
    }
    float ts = block_sum(s);
    __syncthreads();
    float ts2 = block_sum(s2);
    if (threadIdx.x == 0) {
        atomicAdd(&part[grp * 2],     ts);
        atomicAdd(&part[grp * 2 + 1], ts2);
    }
}
__global__ void __launch_bounds__(64)
gn_final(const float* __restrict__ part) {
    int i = threadIdx.x;   // 0..63
    const float invn = 1.f / (GCH * NSP);
    float mean = part[i * 2] * invn;
    float var  = part[i * 2 + 1] * invn - mean * mean;
    g_mean[i] = mean;
    g_inv[i]  = rsqrtf(var + 1e-6f);
}

// ---------------- weights -> half, biases -> packed ----------------
__global__ void __launch_bounds__(256)
round_weights(const float* __restrict__ w0, const float* __restrict__ w1,
              const float* __restrict__ w2, const float* __restrict__ w3,
              __half* __restrict__ o) {
    const int N = C_DIM * C_DIM;
    const float* src[4] = { w0, w1, w2, w3 };
    int which = blockIdx.y;
    const float4* s = (const float4*)src[which];
    __half2* d = (__half2*)(o + (size_t)which * N);
    for (int i = blockIdx.x * 256 + threadIdx.x; i < N / 4; i += gridDim.x * 256) {
        float4 v = s[i];
        d[i * 2]     = __floats2half2_rn(v.x, v.y);
        d[i * 2 + 1] = __floats2half2_rn(v.z, v.w);
    }
}
__global__ void __launch_bounds__(256)
pack_bias(const float* __restrict__ bq, const float* __restrict__ bk,
          const float* __restrict__ bv, float* __restrict__ o) {
    int i = blockIdx.x * 256 + threadIdx.x;
    if (i < C_DIM) o[i] = bq[i];
    else if (i < 2 * C_DIM) o[i] = bk[i - C_DIM];
    else if (i < 3 * C_DIM) o[i] = bv[i - 2 * C_DIM];
}

// ---------------- normalize + transpose: x[b][c][n] -> hnT[b][n][c], 64x64 tiles ----------------
__global__ void __launch_bounds__(256)
gn_norm_transpose(const float* __restrict__ x, const float* __restrict__ gamma,
                  const float* __restrict__ beta, __half* __restrict__ hnT) {
    __shared__ float tile[64][65];
    const int b  = blockIdx.z;
    const int n0 = blockIdx.x * 64, c0 = blockIdx.y * 64;
    const int tid = threadIdx.x;
    const float* xb = x + (size_t)b * C_DIM * NSP;

    // load: 64 c-rows x 16 float4 (n)
    {
        const int q  = tid & 15;          // float4 index in row
        const int cr = tid >> 4;          // 0..15
        #pragma unroll
        for (int r = 0; r < 4; r++) {
            int c = cr + r * 16;
            int cg = c0 + c;
            int grp = b * NGROUPS + (cg >> 4);
            float gm = gamma[cg] * g_inv[grp];
            float bt = beta[cg] - g_mean[grp] * gm;
            float4 v = *(const float4*)(xb + (size_t)cg * NSP + n0 + q * 4);
            tile[c][q * 4 + 0] = v.x * gm + bt;
            tile[c][q * 4 + 1] = v.y * gm + bt;
            tile[c][q * 4 + 2] = v.z * gm + bt;
            tile[c][q * 4 + 3] = v.w * gm + bt;
        }
    }
    __syncthreads();
    // store: 64 n-rows x 32 half2 (c)
    {
        const int h2 = tid & 31;          // c-pair 0..31
        const int nr = tid >> 5;          // 0..7
        __half* hb = hnT + (size_t)b * NSP * C_DIM + c0 + h2 * 2;
        #pragma unroll
        for (int r = 0; r < 8; r++) {
            int n = nr + r * 8;
            *(__half2*)(hb + (size_t)(n0 + n) * C_DIM) =
                __floats2half2_rn(tile[h2 * 2][n], tile[h2 * 2 + 1][n]);
        }
    }
}

// ---------------- launch ----------------
extern "C" void kernel_launch(void* const* d_in, const int* in_sizes, int n_in,
                              void* d_out, int out_size) {
    const float* x     = (const float*)d_in[0];
    const float* gamma = (const float*)d_in[1];
    const float* beta  = (const float*)d_in[2];
    const float* wq = (const float*)d_in[3];  const float* bq = (const float*)d_in[4];
    const float* wk = (const float*)d_in[5];  const float* bk = (const float*)d_in[6];
    const float* wv = (const float*)d_in[7];  const float* bv = (const float*)d_in[8];
    const float* wo = (const float*)d_in[9];  const float* bo = (const float*)d_in[10];
    float* out = (float*)d_out;

    __half *hnT, *q, *k, *v, *ao, *at, *wh;
    float *rsum, *part, *bqkv;
    cudaGetSymbolAddress((void**)&hnT, g_hnT);
    cudaGetSymbolAddress((void**)&q,   g_q);
    cudaGetSymbolAddress((void**)&k,   g_k);
    cudaGetSymbolAddress((void**)&v,   g_v);
    cudaGetSymbolAddress((void**)&ao,  g_ao);
    cudaGetSymbolAddress((void**)&at,  g_at);
    cudaGetSymbolAddress((void**)&rsum, g_rsum);
    cudaGetSymbolAddress((void**)&part, g_part);
    cudaGetSymbolAddress((void**)&wh,  g_wh);
    cudaGetSymbolAddress((void**)&bqkv, g_bqkv);

    cudaFuncSetAttribute(hgemm, cudaFuncAttributeMaxDynamicSharedMemorySize, SMEM_DYN);

    const float scale = 0.044194173824159216f;   // 512^-0.5

    zero_scratch<<<BATCH * NSP / 1024, 1024>>>(rsum, part);
    round_weights<<<dim3(64, 4), 256>>>(wq, wk, wv, wo, wh);
    pack_bias<<<6, 256>>>(bq, bk, bv, bqkv);
    gn_part<<<BATCH * NGROUPS * 8, 256>>>(x, part);
    gn_final<<<1, 64>>>(part);
    gn_norm_transpose<<<dim3(NSP/64, C_DIM/64, BATCH), 256>>>(x, gamma, beta, hnT);

    // fused QKV: M=4096 x N=1536 x K=512
    dim3 gqkv(1536 / NT, NSP / MT, BATCH);
    hgemm<<<gqkv, NTH, SMEM_DYN>>>(hnT, BO, C_DIM, wh, 0, C_DIM,
                                   512, 1.f, bqkv, q, k, v, nullptr, nullptr, 2);

    // exp-scores + row sums
    dim3 gsc(NSP / NT, NSP / MT, BATCH);
    hgemm<<<gsc, NTH, SMEM_DYN>>>(q, BO, C_DIM, k, BO, C_DIM,
                                  512, scale, nullptr, at, nullptr, nullptr, nullptr, rsum, 0);

    // ao[i,c] = (at[i,:] . v[c,:]) / rsum[i]
    dim3 gav(C_DIM / NT, NSP / MT, BATCH);
    hgemm<<<gav, NTH, SMEM_DYN>>>(at, SO, NSP, v, BO, NSP,
                                  NSP, 1.f, nullptr, ao, nullptr, nullptr, nullptr, rsum, 1);

    // out[c][token] = ao . wo^T + bo + x
    hgemm<<<gav, NTH, SMEM_DYN>>>(ao, BO, C_DIM, wh + 3 * WO, 0, C_DIM,
                                  512, 1.f, bo, out, nullptr, nullptr, x, nullptr, 3);
}

// round 12
// speedup vs baseline: 1.0377x; 1.0377x over previous
#include <cuda_runtime.h>
#include <cuda_fp16.h>
#include <cstdint>
#include <cstddef>

#define C_DIM 512
#define NSP   4096
#define BATCH 2
#define NGROUPS 32
#define GCH 16

#define MT 128
#define NT 128
#define KC 64                         // halves per chunk
#define KPADW 36                      // words per row (32 data + 4 pad)
#define STAGE_WORDS (MT * KPADW)      // 4608 words = 18KB per tile
#define NSTAGE 3
#define SMEM_DYN (NSTAGE * 2 * STAGE_WORDS * 4)   // 110592 B

#define BO  ((size_t)C_DIM * NSP)
#define SO  ((size_t)NSP * NSP)
#define WO  ((size_t)C_DIM * C_DIM)

// ---------------- scratch ----------------
__device__ __half g_hnT[(size_t)BATCH * NSP * C_DIM];   // [b][token][cin]
__device__ __half g_q  [(size_t)BATCH * NSP * C_DIM];
__device__ __half g_k  [(size_t)BATCH * NSP * C_DIM];
__device__ __half g_v  [(size_t)BATCH * C_DIM * NSP];   // [b][cout][token]
__device__ __half g_ao [(size_t)BATCH * NSP * C_DIM];
__device__ __half g_at [(size_t)BATCH * NSP * NSP];     // exp(scores), unnormalized
__device__ float  g_rsum[BATCH * NSP];
__device__ float  g_part[BATCH * NGROUPS * 2];
__device__ __half g_wh [4 * C_DIM * C_DIM];
__device__ float  g_bqkv[3 * C_DIM];
__device__ float  g_mean[BATCH * NGROUPS];
__device__ float  g_inv [BATCH * NGROUPS];

__device__ __forceinline__ void cp16(uint32_t smem_dst, const void* gsrc) {
    asm volatile("cp.async.cg.shared.global [%0], [%1], 16;" :: "r"(smem_dst), "l"(gsrc));
}
#define CP_COMMIT() asm volatile("cp.async.commit_group;" ::: "memory")
#define CP_WAIT2()  asm volatile("cp.async.wait_group 2;" ::: "memory")

__device__ __forceinline__ void mma_f16(float* d, const uint32_t* a, const uint32_t* b) {
    asm volatile(
        "mma.sync.aligned.m16n8k16.row.col.f32.f16.f16.f32 "
        "{%0,%1,%2,%3}, {%4,%5,%6,%7}, {%8,%9}, {%0,%1,%2,%3};"
        : "+f"(d[0]), "+f"(d[1]), "+f"(d[2]), "+f"(d[3])
        : "r"(a[0]), "r"(a[1]), "r"(a[2]), "r"(a[3]), "r"(b[0]), "r"(b[1]));
}
__device__ __forceinline__ void ldsm_x4(uint32_t& r0, uint32_t& r1, uint32_t& r2,
                                        uint32_t& r3, uint32_t addr) {
    asm volatile("ldmatrix.sync.aligned.m8n8.x4.shared.b16 {%0,%1,%2,%3}, [%4];"
                 : "=r"(r0), "=r"(r1), "=r"(r2), "=r"(r3) : "r"(addr));
}

// ---------------- fp16 GEMM: 128x128 tile, 256 threads, 2 CTA/SM, cp.async 3-stage ----------------
// D[m,n] = alpha * sum_k A[m,k]*B[n,k]
// mode 0: at half [m][4096] = exp(D); atomicAdd row sums
// mode 1: C0 half [m][512] = D / rsum[m]
// mode 2: fused QKV: n<512 -> q; n<1024 -> k; else v trans [c][4096]
// mode 3: C0 float [n][4096] trans + bias[n] + resid
__global__ void __launch_bounds__(256, 2)
hgemm(const __half* __restrict__ A, size_t aBat, int lda,
      const __half* __restrict__ B, size_t bBat, int ldb,
      int K, float alpha, const float* __restrict__ bias,
      void* C0, void* C1, void* C2,
      const float* __restrict__ resid, float* __restrict__ rsum, int mode) {
    extern __shared__ uint32_t sm[];

    const int tid  = threadIdx.x;
    const int wid  = tid >> 5, lane = tid & 31;
    const int wm   = wid & 1;
    const int wn   = wid >> 1;
    const int g    = lane >> 2;
    const int t    = lane & 3;

    const int m0 = blockIdx.y * MT, n0 = blockIdx.x * NT;
    const int z  = blockIdx.z;
    A += z * aBat + (size_t)m0 * lda;
    B += z * bBat + (size_t)n0 * ldb;

    const int row  = tid >> 3;
    const int colw = (tid & 7) << 2;
    const int colh = (tid & 7) << 3;

    uint32_t smbase;
    asm("{ .reg .u64 t; cvta.to.shared.u64 t, %1; cvt.u32.u64 %0, t; }"
        : "=r"(smbase) : "l"((void*)sm));

    const uint32_t aoff = (((uint32_t)(wm * 64 + (lane & 15)) * KPADW) + ((lane >> 4) << 2)) * 4;
    const uint32_t boff = (((uint32_t)(wn * 32 + (lane & 7) + ((lane >> 4) << 3)) * KPADW)
                           + (((lane >> 3) & 1) << 2)) * 4;

    const int nch = K / KC;
    float acc[4][4][4] = {};

    #define ISSUE(cidx)  do {                                                        \
        const int _b  = (cidx) % NSTAGE;                                             \
        const int _kc = (cidx) * KC;                                                 \
        uint32_t _sa = smbase + ((_b * 2 * STAGE_WORDS) + row * KPADW + colw) * 4;   \
        uint32_t _sb = _sa + STAGE_WORDS * 4;                                        \
        _Pragma("unroll")                                                            \
        for (int _i = 0; _i < 4; _i++) {                                             \
            cp16(_sa + _i * 32 * KPADW * 4,                                          \
                 A + (size_t)(row + _i * 32) * lda + _kc + colh);                    \
            cp16(_sb + _i * 32 * KPADW * 4,                                          \
                 B + (size_t)(row + _i * 32) * ldb + _kc + colh);                    \
        }                                                                            \
    } while (0)

    ISSUE(0); CP_COMMIT();
    ISSUE(1); CP_COMMIT();

    for (int c = 0; c < nch; c++) {
        if (c + 2 < nch) { ISSUE(c + 2); }
        CP_COMMIT();
        CP_WAIT2();
        __syncthreads();

        const uint32_t sA = smbase + (c % NSTAGE) * 2 * STAGE_WORDS * 4;
        const uint32_t sB = sA + STAGE_WORDS * 4;
        #pragma unroll
        for (int ks = 0; ks < 4; ks++) {
            uint32_t af[4][4], bf[4][2];
            #pragma unroll
            for (int mi = 0; mi < 4; mi++)
                ldsm_x4(af[mi][0], af[mi][1], af[mi][2], af[mi][3],
                        sA + aoff + mi * (16 * KPADW * 4) + ks * 32);
            #pragma unroll
            for (int nj = 0; nj < 2; nj++)
                ldsm_x4(bf[2 * nj][0], bf[2 * nj][1], bf[2 * nj + 1][0], bf[2 * nj + 1][1],
                        sB + boff + nj * (16 * KPADW * 4) + ks * 32);
            #pragma unroll
            for (int mi = 0; mi < 4; mi++)
                #pragma unroll
                for (int ni = 0; ni < 4; ni++)
                    mma_f16(acc[mi][ni], af[mi], bf[ni]);
        }
        __syncthreads();
    }
    #undef ISSUE

    // -------- epilogue --------
    #pragma unroll
    for (int mi = 0; mi < 4; mi++) {
        int m = m0 + wm * 64 + mi * 16 + g;
        float rs0 = 0.f, rs1 = 0.f;
        float ri0 = 1.f, ri1 = 1.f;
        if (mode == 1) {
            ri0 = __frcp_rn(rsum[z * NSP + m]);
            ri1 = __frcp_rn(rsum[z * NSP + m + 8]);
        }
        #pragma unroll
        for (int ni = 0; ni < 4; ni++) {
            const float* d = acc[mi][ni];
            int n = n0 + wn * 32 + ni * 8 + t * 2;
            float b0 = bias ? bias[n]     : 0.f;
            float b1 = bias ? bias[n + 1] : 0.f;
            float v0 = d[0] * alpha + b0;
            float v1 = d[1] * alpha + b1;
            float v2 = d[2] * alpha + b0;
            float v3 = d[3] * alpha + b1;
            if (mode == 0) {
                v0 = __expf(v0); v1 = __expf(v1);
                v2 = __expf(v2); v3 = __expf(v3);
                rs0 += v0 + v1; rs1 += v2 + v3;
                __half* o = (__half*)C0 + z * SO;
                *(__half2*)(o + (size_t)m * NSP + n)       = __floats2half2_rn(v0, v1);
                *(__half2*)(o + (size_t)(m + 8) * NSP + n) = __floats2half2_rn(v2, v3);
            } else if (mode == 1) {
                __half* o = (__half*)C0 + z * BO;
                *(__half2*)(o + (size_t)m * C_DIM + n)       = __floats2half2_rn(v0 * ri0, v1 * ri0);
                *(__half2*)(o + (size_t)(m + 8) * C_DIM + n) = __floats2half2_rn(v2 * ri1, v3 * ri1);
            } else if (mode == 2) {
                if (n < 1024) {
                    __half* o = (__half*)((n < 512) ? C0 : C1) + z * BO;
                    int nn = n & 511;
                    *(__half2*)(o + (size_t)m * C_DIM + nn)       = __floats2half2_rn(v0, v1);
                    *(__half2*)(o + (size_t)(m + 8) * C_DIM + nn) = __floats2half2_rn(v2, v3);
                } else {
                    __half* o = (__half*)C2 + z * BO;
                    int nn = n - 1024;
                    o[(size_t)nn * NSP + m]           = __float2half_rn(v0);
                    o[(size_t)(nn + 1) * NSP + m]     = __float2half_rn(v1);
                    o[(size_t)nn * NSP + m + 8]       = __float2half_rn(v2);
                    o[(size_t)(nn + 1) * NSP + m + 8] = __float2half_rn(v3);
                }
            } else {
                float* o = (float*)C0 + z * BO;
                const float* r = resid + z * BO;
                size_t o0 = (size_t)n * NSP + m;
                size_t o1 = (size_t)(n + 1) * NSP + m;
                o[o0]     = v0 + r[o0];
                o[o1]     = v1 + r[o1];
                o[o0 + 8] = v2 + r[o0 + 8];
                o[o1 + 8] = v3 + r[o1 + 8];
            }
        }
        if (mode == 0) {
            rs0 += __shfl_xor_sync(0xffffffffu, rs0, 1);
            rs0 += __shfl_xor_sync(0xffffffffu, rs0, 2);
            rs1 += __shfl_xor_sync(0xffffffffu, rs1, 1);
            rs1 += __shfl_xor_sync(0xffffffffu, rs1, 2);
            if (t == 0) {
                atomicAdd(&rsum[z * NSP + m], rs0);
                atomicAdd(&rsum[z * NSP + m + 8], rs1);
            }
        }
    }
}

// ---------------- zero rsum + GN partials ----------------
__global__ void __launch_bounds__(1024)
zero_scratch(float* __restrict__ rsum, float* __restrict__ part) {
    int i = blockIdx.x * 1024 + threadIdx.x;
    if (i < BATCH * NSP) rsum[i] = 0.f;
    if (i < BATCH * NGROUPS * 2) part[i] = 0.f;
}

// ---------------- block reduction ----------------
__device__ __forceinline__ float block_sum(float v) {
    __shared__ float smr[32];
    int w = threadIdx.x >> 5, l = threadIdx.x & 31;
    #pragma unroll
    for (int o = 16; o; o >>= 1) v += __shfl_xor_sync(0xffffffffu, v, o);
    __syncthreads();
    if (l == 0) smr[w] = v;
    __syncthreads();
    if (w == 0) {
        v = (l < (int)(blockDim.x >> 5)) ? smr[l] : 0.f;
        #pragma unroll
        for (int o = 16; o; o >>= 1) v += __shfl_xor_sync(0xffffffffu, v, o);
        if (l == 0) smr[0] = v;
    }
    __syncthreads();
    return smr[0];
}

// ---------------- GN partial stats: 1024 blocks (16 slices per group) ----------------
__global__ void __launch_bounds__(256)
gn_part(const float* __restrict__ x, float* __restrict__ part) {
    const int grp = blockIdx.x >> 4;           // 0..63 (b*32+g)
    const int sl  = blockIdx.x & 15;
    const size_t base = (size_t)grp * GCH * NSP + (size_t)sl * (GCH * NSP / 16);
    const float4* xp = (const float4*)(x + base);
    const int NV = GCH * NSP / 16 / 4;         // 1024 float4
    float s = 0.f, s2 = 0.f;
    for (int i = threadIdx.x; i < NV; i += 256) {
        float4 v = xp[i];
        s  += v.x + v.y + v.z + v.w;
        s2 += v.x*v.x + v.y*v.y + v.z*v.z + v.w*v.w;
    }
    float ts = block_sum(s);
    __syncthreads();
    float ts2 = block_sum(s2);
    if (threadIdx.x == 0) {
        atomicAdd(&part[grp * 2],     ts);
        atomicAdd(&part[grp * 2 + 1], ts2);
    }
}
__global__ void __launch_bounds__(64)
gn_final(const float* __restrict__ part) {
    int i = threadIdx.x;
    const float invn = 1.f / (GCH * NSP);
    float mean = part[i * 2] * invn;
    float var  = part[i * 2 + 1] * invn - mean * mean;
    g_mean[i] = mean;
    g_inv[i]  = rsqrtf(var + 1e-6f);
}

// ---------------- weights -> half, biases -> packed ----------------
__global__ void __launch_bounds__(256)
round_weights(const float* __restrict__ w0, const float* __restrict__ w1,
              const float* __restrict__ w2, const float* __restrict__ w3,
              __half* __restrict__ o) {
    const int N = C_DIM * C_DIM;
    const float* src[4] = { w0, w1, w2, w3 };
    int which = blockIdx.y;
    const float4* s = (const float4*)src[which];
    __half2* d = (__half2*)(o + (size_t)which * N);
    for (int i = blockIdx.x * 256 + threadIdx.x; i < N / 4; i += gridDim.x * 256) {
        float4 v = s[i];
        d[i * 2]     = __floats2half2_rn(v.x, v.y);
        d[i * 2 + 1] = __floats2half2_rn(v.z, v.w);
    }
}
__global__ void __launch_bounds__(256)
pack_bias(const float* __restrict__ bq, const float* __restrict__ bk,
          const float* __restrict__ bv, float* __restrict__ o) {
    int i = blockIdx.x * 256 + threadIdx.x;
    if (i < C_DIM) o[i] = bq[i];
    else if (i < 2 * C_DIM) o[i] = bk[i - C_DIM];
    else if (i < 3 * C_DIM) o[i] = bv[i - 2 * C_DIM];
}

// ---------------- normalize + transpose: x[b][c][n] -> hnT[b][n][c], 64x64 tiles ----------------
__global__ void __launch_bounds__(256)
gn_norm_transpose(const float* __restrict__ x, const float* __restrict__ gamma,
                  const float* __restrict__ beta, __half* __restrict__ hnT) {
    __shared__ float tile[64][65];
    const int b  = blockIdx.z;
    const int n0 = blockIdx.x * 64, c0 = blockIdx.y * 64;
    const int tid = threadIdx.x;
    const float* xb = x + (size_t)b * C_DIM * NSP;

    {
        const int q  = tid & 15;
        const int cr = tid >> 4;
        #pragma unroll
        for (int r = 0; r < 4; r++) {
            int c = cr + r * 16;
            int cg = c0 + c;
            int grp = b * NGROUPS + (cg >> 4);
            float gm = gamma[cg] * g_inv[grp];
            float bt = beta[cg] - g_mean[grp] * gm;
            float4 v = *(const float4*)(xb + (size_t)cg * NSP + n0 + q * 4);
            tile[c][q * 4 + 0] = v.x * gm + bt;
            tile[c][q * 4 + 1] = v.y * gm + bt;
            tile[c][q * 4 + 2] = v.z * gm + bt;
            tile[c][q * 4 + 3] = v.w * gm + bt;
        }
    }
    __syncthreads();
    {
        const int h2 = tid & 31;
        const int nr = tid >> 5;
        __half* hb = hnT + (size_t)b * NSP * C_DIM + c0 + h2 * 2;
        #pragma unroll
        for (int r = 0; r < 8; r++) {
            int n = nr + r * 8;
            *(__half2*)(hb + (size_t)(n0 + n) * C_DIM) =
                __floats2half2_rn(tile[h2 * 2][n], tile[h2 * 2 + 1][n]);
        }
    }
}

// ---------------- launch ----------------
extern "C" void kernel_launch(void* const* d_in, const int* in_sizes, int n_in,
                              void* d_out, int out_size) {
    const float* x     = (const float*)d_in[0];
    const float* gamma = (const float*)d_in[1];
    const float* beta  = (const float*)d_in[2];
    const float* wq = (const float*)d_in[3];  const float* bq = (const float*)d_in[4];
    const float* wk = (const float*)d_in[5];  const float* bk = (const float*)d_in[6];
    const float* wv = (const float*)d_in[7];  const float* bv = (const float*)d_in[8];
    const float* wo = (const float*)d_in[9];  const float* bo = (const float*)d_in[10];
    float* out = (float*)d_out;

    __half *hnT, *q, *k, *v, *ao, *at, *wh;
    float *rsum, *part, *bqkv;
    cudaGetSymbolAddress((void**)&hnT, g_hnT);
    cudaGetSymbolAddress((void**)&q,   g_q);
    cudaGetSymbolAddress((void**)&k,   g_k);
    cudaGetSymbolAddress((void**)&v,   g_v);
    cudaGetSymbolAddress((void**)&ao,  g_ao);
    cudaGetSymbolAddress((void**)&at,  g_at);
    cudaGetSymbolAddress((void**)&rsum, g_rsum);
    cudaGetSymbolAddress((void**)&part, g_part);
    cudaGetSymbolAddress((void**)&wh,  g_wh);
    cudaGetSymbolAddress((void**)&bqkv, g_bqkv);

    cudaFuncSetAttribute(hgemm, cudaFuncAttributeMaxDynamicSharedMemorySize, SMEM_DYN);

    const float scale = 0.044194173824159216f;   // 512^-0.5

    zero_scratch<<<BATCH * NSP / 1024, 1024>>>(rsum, part);
    round_weights<<<dim3(64, 4), 256>>>(wq, wk, wv, wo, wh);
    pack_bias<<<6, 256>>>(bq, bk, bv, bqkv);
    gn_part<<<BATCH * NGROUPS * 16, 256>>>(x, part);
    gn_final<<<1, 64>>>(part);
    gn_norm_transpose<<<dim3(NSP/64, C_DIM/64, BATCH), 256>>>(x, gamma, beta, hnT);

    // fused QKV: M=4096 x N=1536 x K=512
    dim3 gqkv(1536 / NT, NSP / MT, BATCH);
    hgemm<<<gqkv, 256, SMEM_DYN>>>(hnT, BO, C_DIM, wh, 0, C_DIM,
                                   512, 1.f, bqkv, q, k, v, nullptr, nullptr, 2);

    // exp-scores + row sums
    dim3 gsc(NSP / NT, NSP / MT, BATCH);
    hgemm<<<gsc, 256, SMEM_DYN>>>(q, BO, C_DIM, k, BO, C_DIM,
                                  512, scale, nullptr, at, nullptr, nullptr, nullptr, rsum, 0);

    // ao[i,c] = (at[i,:] . v[c,:]) / rsum[i]
    dim3 gav(C_DIM / NT, NSP / MT, BATCH);
    hgemm<<<gav, 256, SMEM_DYN>>>(at, SO, NSP, v, BO, NSP,
                                  NSP, 1.f, nullptr, ao, nullptr, nullptr, nullptr, rsum, 1);

    // out[c][token] = ao . wo^T + bo + x
    hgemm<<<gav, 256, SMEM_DYN>>>(ao, BO, C_DIM, wh + 3 * WO, 0, C_DIM,
                                  512, 1.f, bo, out, nullptr, nullptr, x, nullptr, 3);
}

// round 15
// speedup vs baseline: 1.0847x; 1.0454x over previous
#include <cuda_runtime.h>
#include <cuda_fp16.h>
#include <cstdint>
#include <cstddef>

#define C_DIM 512
#define NSP   4096
#define BATCH 2
#define NGROUPS 32
#define GCH 16

#define MT 128
#define NT 128
#define KC 64                         // halves per chunk
#define KPADW 36                      // words per row (32 data + 4 pad)
#define STAGE_WORDS (MT * KPADW)      // 4608 words = 18KB per tile
#define NSTAGE 3
#define SMEM_DYN (NSTAGE * 2 * STAGE_WORDS * 4)   // 110592 B

#define BO  ((size_t)C_DIM * NSP)
#define SO  ((size_t)NSP * NSP)
#define WO  ((size_t)C_DIM * C_DIM)

// ---------------- scratch ----------------
__device__ __half g_hnT[(size_t)BATCH * NSP * C_DIM];   // [b][token][cin]
__device__ __half g_q  [(size_t)BATCH * NSP * C_DIM];
__device__ __half g_k  [(size_t)BATCH * NSP * C_DIM];
__device__ __half g_v  [(size_t)BATCH * C_DIM * NSP];   // [b][cout][token]
__device__ __half g_ao [(size_t)BATCH * NSP * C_DIM];
__device__ __half g_at [(size_t)BATCH * NSP * NSP];     // exp(scores), unnormalized
__device__ float  g_rsum[BATCH * NSP];
__device__ float  g_part[BATCH * NGROUPS * 2];
__device__ __half g_wh [4 * C_DIM * C_DIM];
__device__ float  g_bqkv[3 * C_DIM];

__device__ __forceinline__ void cp16(uint32_t smem_dst, const void* gsrc) {
    asm volatile("cp.async.cg.shared.global [%0], [%1], 16;" :: "r"(smem_dst), "l"(gsrc));
}
#define CP_COMMIT() asm volatile("cp.async.commit_group;" ::: "memory")
#define CP_WAIT1()  asm volatile("cp.async.wait_group 1;" ::: "memory")

__device__ __forceinline__ void mma_f16(float* d, const uint32_t* a, const uint32_t* b) {
    asm volatile(
        "mma.sync.aligned.m16n8k16.row.col.f32.f16.f16.f32 "
        "{%0,%1,%2,%3}, {%4,%5,%6,%7}, {%8,%9}, {%0,%1,%2,%3};"
        : "+f"(d[0]), "+f"(d[1]), "+f"(d[2]), "+f"(d[3])
        : "r"(a[0]), "r"(a[1]), "r"(a[2]), "r"(a[3]), "r"(b[0]), "r"(b[1]));
}
__device__ __forceinline__ void ldsm_x4(uint32_t& r0, uint32_t& r1, uint32_t& r2,
                                        uint32_t& r3, uint32_t addr) {
    asm volatile("ldmatrix.sync.aligned.m8n8.x4.shared.b16 {%0,%1,%2,%3}, [%4];"
                 : "=r"(r0), "=r"(r1), "=r"(r2), "=r"(r3) : "r"(addr));
}

// ---------------- fp16 GEMM: 128x128 tile, 256 threads, 2 CTA/SM, single-sync pipeline ----
// D[m,n] = alpha * sum_k A[m,k]*B[n,k]
// mode 0: at half [m][4096] = exp2(D*alpha); atomicAdd row sums  (alpha pre-scaled by log2e)
// mode 1: C0 half [m][512] = D / rsum[m]
// mode 2: fused QKV: n<512 -> q; n<1024 -> k; else v trans [c][4096]
// mode 3: C0 float [n][4096] trans + bias[n] + resid
__global__ void __launch_bounds__(256, 2)
hgemm(const __half* __restrict__ A, size_t aBat, int lda,
      const __half* __restrict__ B, size_t bBat, int ldb,
      int K, float alpha, const float* __restrict__ bias,
      void* C0, void* C1, void* C2,
      const float* __restrict__ resid, float* __restrict__ rsum, int mode) {
    extern __shared__ uint32_t sm[];

    const int tid  = threadIdx.x;
    const int wid  = tid >> 5, lane = tid & 31;
    const int wm   = wid & 1;
    const int wn   = wid >> 1;
    const int g    = lane >> 2;
    const int t    = lane & 3;

    const int m0 = blockIdx.y * MT, n0 = blockIdx.x * NT;
    const int z  = blockIdx.z;
    A += z * aBat + (size_t)m0 * lda;
    B += z * bBat + (size_t)n0 * ldb;

    const int row  = tid >> 3;
    const int colw = (tid & 7) << 2;
    const int colh = (tid & 7) << 3;

    uint32_t smbase;
    asm("{ .reg .u64 t; cvta.to.shared.u64 t, %1; cvt.u32.u64 %0, t; }"
        : "=r"(smbase) : "l"((void*)sm));

    const uint32_t aoff = (((uint32_t)(wm * 64 + (lane & 15)) * KPADW) + ((lane >> 4) << 2)) * 4;
    const uint32_t boff = (((uint32_t)(wn * 32 + (lane & 7) + ((lane >> 4) << 3)) * KPADW)
                           + (((lane >> 3) & 1) << 2)) * 4;

    const int nch = K / KC;
    float acc[4][4][4] = {};

    #define ISSUE(cidx)  do {                                                        \
        const int _b  = (cidx) % NSTAGE;                                             \
        const int _kc = (cidx) * KC;                                                 \
        uint32_t _sa = smbase + ((_b * 2 * STAGE_WORDS) + row * KPADW + colw) * 4;   \
        uint32_t _sb = _sa + STAGE_WORDS * 4;                                        \
        _Pragma("unroll")                                                            \
        for (int _i = 0; _i < 4; _i++) {                                             \
            cp16(_sa + _i * 32 * KPADW * 4,                                          \
                 A + (size_t)(row + _i * 32) * lda + _kc + colh);                    \
            cp16(_sb + _i * 32 * KPADW * 4,                                          \
                 B + (size_t)(row + _i * 32) * ldb + _kc + colh);                    \
        }                                                                            \
    } while (0)

    ISSUE(0); CP_COMMIT();
    ISSUE(1); CP_COMMIT();

    for (int c = 0; c < nch; c++) {
        CP_WAIT1();                 // groups 0..c+1 committed; <=1 pending => chunk c ready
        __syncthreads();            // all warps done reading stage (c-1)%3
        if (c + 2 < nch) { ISSUE(c + 2); }   // writes stage (c-1)%3 — safe after sync
        CP_COMMIT();                // always commit (possibly empty) to keep group numbering

        const uint32_t sA = smbase + (c % NSTAGE) * 2 * STAGE_WORDS * 4;
        const uint32_t sB = sA + STAGE_WORDS * 4;
        #pragma unroll
        for (int ks = 0; ks < 4; ks++) {
            uint32_t af[4][4], bf[4][2];
            #pragma unroll
            for (int mi = 0; mi < 4; mi++)
                ldsm_x4(af[mi][0], af[mi][1], af[mi][2], af[mi][3],
                        sA + aoff + mi * (16 * KPADW * 4) + ks * 32);
            #pragma unroll
            for (int nj = 0; nj < 2; nj++)
                ldsm_x4(bf[2 * nj][0], bf[2 * nj][1], bf[2 * nj + 1][0], bf[2 * nj + 1][1],
                        sB + boff + nj * (16 * KPADW * 4) + ks * 32);
            #pragma unroll
            for (int mi = 0; mi < 4; mi++)
                #pragma unroll
                for (int ni = 0; ni < 4; ni++)
                    mma_f16(acc[mi][ni], af[mi], bf[ni]);
        }
    }
    #undef ISSUE

    // -------- epilogue --------
    #pragma unroll
    for (int mi = 0; mi < 4; mi++) {
        int m = m0 + wm * 64 + mi * 16 + g;
        float rs0 = 0.f, rs1 = 0.f;
        float ri0 = 1.f, ri1 = 1.f;
        if (mode == 1) {
            ri0 = __frcp_rn(rsum[z * NSP + m]);
            ri1 = __frcp_rn(rsum[z * NSP + m + 8]);
        }
        #pragma unroll
        for (int ni = 0; ni < 4; ni++) {
            const float* d = acc[mi][ni];
            int n = n0 + wn * 32 + ni * 8 + t * 2;
            float b0 = bias ? bias[n]     : 0.f;
            float b1 = bias ? bias[n + 1] : 0.f;
            float v0 = d[0] * alpha + b0;
            float v1 = d[1] * alpha + b1;
            float v2 = d[2] * alpha + b0;
            float v3 = d[3] * alpha + b1;
            if (mode == 0) {
                v0 = exp2f(v0); v1 = exp2f(v1);
                v2 = exp2f(v2); v3 = exp2f(v3);
                rs0 += v0 + v1; rs1 += v2 + v3;
                __half* o = (__half*)C0 + z * SO;
                *(__half2*)(o + (size_t)m * NSP + n)       = __floats2half2_rn(v0, v1);
                *(__half2*)(o + (size_t)(m + 8) * NSP + n) = __floats2half2_rn(v2, v3);
            } else if (mode == 1) {
                __half* o = (__half*)C0 + z * BO;
                *(__half2*)(o + (size_t)m * C_DIM + n)       = __floats2half2_rn(v0 * ri0, v1 * ri0);
                *(__half2*)(o + (size_t)(m + 8) * C_DIM + n) = __floats2half2_rn(v2 * ri1, v3 * ri1);
            } else if (mode == 2) {
                if (n < 1024) {
                    __half* o = (__half*)((n < 512) ? C0 : C1) + z * BO;
                    int nn = n & 511;
                    *(__half2*)(o + (size_t)m * C_DIM + nn)       = __floats2half2_rn(v0, v1);
                    *(__half2*)(o + (size_t)(m + 8) * C_DIM + nn) = __floats2half2_rn(v2, v3);
                } else {
                    __half* o = (__half*)C2 + z * BO;
                    int nn = n - 1024;
                    o[(size_t)nn * NSP + m]           = __float2half_rn(v0);
                    o[(size_t)(nn + 1) * NSP + m]     = __float2half_rn(v1);
                    o[(size_t)nn * NSP + m + 8]       = __float2half_rn(v2);
                    o[(size_t)(nn + 1) * NSP + m + 8] = __float2half_rn(v3);
                }
            } else {
                float* o = (float*)C0 + z * BO;
                const float* r = resid + z * BO;
                size_t o0 = (size_t)n * NSP + m;
                size_t o1 = (size_t)(n + 1) * NSP + m;
                o[o0]     = v0 + r[o0];
                o[o1]     = v1 + r[o1];
                o[o0 + 8] = v2 + r[o0 + 8];
                o[o1 + 8] = v3 + r[o1 + 8];
            }
        }
        if (mode == 0) {
            rs0 += __shfl_xor_sync(0xffffffffu, rs0, 1);
            rs0 += __shfl_xor_sync(0xffffffffu, rs0, 2);
            rs1 += __shfl_xor_sync(0xffffffffu, rs1, 1);
            rs1 += __shfl_xor_sync(0xffffffffu, rs1, 2);
            if (t == 0) {
                atomicAdd(&rsum[z * NSP + m], rs0);
                atomicAdd(&rsum[z * NSP + m + 8], rs1);
            }
        }
    }
}

// ---------------- fused prep: weights->half, bias pack, zero rsum/part ----------------
// grid (68, 4): x<64 -> weight convert (which=y); x>=64 -> zero/bias lane
__global__ void __launch_bounds__(256)
prep_kernel(const float* __restrict__ w0, const float* __restrict__ w1,
            const float* __restrict__ w2, const float* __restrict__ w3,
            const float* __restrict__ bq, const float* __restrict__ bk,
            const float* __restrict__ bv,
            __half* __restrict__ wh, float* __restrict__ bqkv,
            float* __restrict__ rsum, float* __restrict__ part) {
    const int N = C_DIM * C_DIM;
    if (blockIdx.x < 64) {
        const float* src[4] = { w0, w1, w2, w3 };
        int which = blockIdx.y;
        const float4* s = (const float4*)src[which];
        __half2* d = (__half2*)(wh + (size_t)which * N);
        for (int i = blockIdx.x * 256 + threadIdx.x; i < N / 4; i += 64 * 256) {
            float4 v = s[i];
            d[i * 2]     = __floats2half2_rn(v.x, v.y);
            d[i * 2 + 1] = __floats2half2_rn(v.z, v.w);
        }
    } else {
        int idx = ((blockIdx.x - 64) * 4 + blockIdx.y) * 256 + threadIdx.x;  // 0..4095
        rsum[idx * 2]     = 0.f;
        rsum[idx * 2 + 1] = 0.f;
        if (idx < BATCH * NGROUPS * 2) part[idx] = 0.f;
        if (idx < C_DIM)            bqkv[idx] = bq[idx];
        else if (idx < 2 * C_DIM)   bqkv[idx] = bk[idx - C_DIM];
        else if (idx < 3 * C_DIM)   bqkv[idx] = bv[idx - 2 * C_DIM];
    }
}

// ---------------- block reduction ----------------
__device__ __forceinline__ float block_sum(float v) {
    __shared__ float smr[32];
    int w = threadIdx.x >> 5, l = threadIdx.x & 31;
    #pragma unroll
    for (int o = 16; o; o >>= 1) v += __shfl_xor_sync(0xffffffffu, v, o);
    __syncthreads();
    if (l == 0) smr[w] = v;
    __syncthreads();
    if (w == 0) {
        v = (l < (int)(blockDim.x >> 5)) ? smr[l] : 0.f;
        #pragma unroll
        for (int o = 16; o; o >>= 1) v += __shfl_xor_sync(0xffffffffu, v, o);
        if (l == 0) smr[0] = v;
    }
    __syncthreads();
    return smr[0];
}

// ---------------- GN partial stats: 1024 blocks (16 slices per group) ----------------
__global__ void __launch_bounds__(256)
gn_part(const float* __restrict__ x, float* __restrict__ part) {
    const int grp = blockIdx.x >> 4;           // 0..63 (b*32+g)
    const int sl  = blockIdx.x & 15;
    const size_t base = (size_t)grp * GCH * NSP + (size_t)sl * (GCH * NSP / 16);
    const float4* xp = (const float4*)(x + base);
    const int NV = GCH * NSP / 16 / 4;         // 1024 float4
    float s = 0.f, s2 = 0.f;
    for (int i = threadIdx.x; i < NV; i += 256) {
        float4 v = xp[i];
        s  += v.x + v.y + v.z + v.w;
        s2 += v.x*v.x + v.y*v.y + v.z*v.z + v.w*v.w;
    }
    float ts = block_sum(s);
    __syncthreads();
    float ts2 = block_sum(s2);
    if (threadIdx.x == 0) {
        atomicAdd(&part[grp * 2],     ts);
        atomicAdd(&part[grp * 2 + 1], ts2);
    }
}

// ---------------- normalize + transpose (stats computed inline from partials) ----------
__global__ void __launch_bounds__(256)
gn_norm_transpose(const float* __restrict__ x, const float* __restrict__ gamma,
                  const float* __restrict__ beta, const float* __restrict__ part,
                  __half* __restrict__ hnT) {
    __shared__ float tile[64][65];
    const int b  = blockIdx.z;
    const int n0 = blockIdx.x * 64, c0 = blockIdx.y * 64;
    const int tid = threadIdx.x;
    const float* xb = x + (size_t)b * C_DIM * NSP;
    const float invn = 1.f / (GCH * NSP);

    {
        const int q  = tid & 15;
        const int cr = tid >> 4;
        #pragma unroll
        for (int r = 0; r < 4; r++) {
            int c = cr + r * 16;
            int cg = c0 + c;
            int grp = b * NGROUPS + (cg >> 4);
            float mean = part[grp * 2] * invn;
            float var  = part[grp * 2 + 1] * invn - mean * mean;
            float inv  = rsqrtf(var + 1e-6f);
            float gm = gamma[cg] * inv;
            float bt = beta[cg] - mean * gm;
            float4 v = *(const float4*)(xb + (size_t)cg * NSP + n0 + q * 4);
            tile[c][q * 4 + 0] = v.x * gm + bt;
            tile[c][q * 4 + 1] = v.y * gm + bt;
            tile[c][q * 4 + 2] = v.z * gm + bt;
            tile[c][q * 4 + 3] = v.w * gm + bt;
        }
    }
    __syncthreads();
    {
        const int h2 = tid & 31;
        const int nr = tid >> 5;
        __half* hb = hnT + (size_t)b * NSP * C_DIM + c0 + h2 * 2;
        #pragma unroll
        for (int r = 0; r < 8; r++) {
            int n = nr + r * 8;
            *(__half2*)(hb + (size_t)(n0 + n) * C_DIM) =
                __floats2half2_rn(tile[h2 * 2][n], tile[h2 * 2 + 1][n]);
        }
    }
}

// ---------------- launch ----------------
extern "C" void kernel_launch(void* const* d_in, const int* in_sizes, int n_in,
                              void* d_out, int out_size) {
    const float* x     = (const float*)d_in[0];
    const float* gamma = (const float*)d_in[1];
    const float* beta  = (const float*)d_in[2];
    const float* wq = (const float*)d_in[3];  const float* bq = (const float*)d_in[4];
    const float* wk = (const float*)d_in[5];  const float* bk = (const float*)d_in[6];
    const float* wv = (const float*)d_in[7];  const float* bv = (const float*)d_in[8];
    const float* wo = (const float*)d_in[9];  const float* bo = (const float*)d_in[10];
    float* out = (float*)d_out;

    __half *hnT, *q, *k, *v, *ao, *at, *wh;
    float *rsum, *part, *bqkv;
    cudaGetSymbolAddress((void**)&hnT, g_hnT);
    cudaGetSymbolAddress((void**)&q,   g_q);
    cudaGetSymbolAddress((void**)&k,   g_k);
    cudaGetSymbolAddress((void**)&v,   g_v);
    cudaGetSymbolAddress((void**)&ao,  g_ao);
    cudaGetSymbolAddress((void**)&at,  g_at);
    cudaGetSymbolAddress((void**)&rsum, g_rsum);
    cudaGetSymbolAddress((void**)&part, g_part);
    cudaGetSymbolAddress((void**)&wh,  g_wh);
    cudaGetSymbolAddress((void**)&bqkv, g_bqkv);

    cudaFuncSetAttribute(hgemm, cudaFuncAttributeMaxDynamicSharedMemorySize, SMEM_DYN);

    const float scale = 0.044194173824159216f;   // 512^-0.5
    const float scale_l2 = scale * 1.4426950408889634f;   // pre-fold log2(e) for exp2

    prep_kernel<<<dim3(68, 4), 256>>>(wq, wk, wv, wo, bq, bk, bv, wh, bqkv, rsum, part);
    gn_part<<<BATCH * NGROUPS * 16, 256>>>(x, part);
    gn_norm_transpose<<<dim3(NSP/64, C_DIM/64, BATCH), 256>>>(x, gamma, beta, part, hnT);

    // fused QKV: M=4096 x N=1536 x K=512
    dim3 gqkv(1536 / NT, NSP / MT, BATCH);
    hgemm<<<gqkv, 256, SMEM_DYN>>>(hnT, BO, C_DIM, wh, 0, C_DIM,
                                   512, 1.f, bqkv, q, k, v, nullptr, nullptr, 2);

    // exp-scores + row sums (exp2 with pre-scaled alpha)
    dim3 gsc(NSP / NT, NSP / MT, BATCH);
    hgemm<<<gsc, 256, SMEM_DYN>>>(q, BO, C_DIM, k, BO, C_DIM,
                                  512, scale_l2, nullptr, at, nullptr, nullptr, nullptr, rsum, 0);

    // ao[i,c] = (at[i,:] . v[c,:]) / rsum[i]
    dim3 gav(C_DIM / NT, NSP / MT, BATCH);
    hgemm<<<gav, 256, SMEM_DYN>>>(at, SO, NSP, v, BO, NSP,
                                  NSP, 1.f, nullptr, ao, nullptr, nullptr, nullptr, rsum, 1);

    // out[c][token] = ao . wo^T + bo + x
    hgemm<<<gav, 256, SMEM_DYN>>>(ao, BO, C_DIM, wh + 3 * WO, 0, C_DIM,
                                  512, 1.f, bo, out, nullptr, nullptr, x, nullptr, 3);
}